// round 10
// baseline (speedup 1.0000x reference)
#include <cuda_runtime.h>
#include <cuda_bf16.h>
#include <cuda_fp16.h>
#include <math.h>

#define NB   2
#define TT   4096
#define HIDD 1024
#define NHH  16
#define DD   64
#define TOPKK 16
#define NEGV (-10000.0f)

// ---------------- device scratch ----------------
__device__ float g_q[(size_t)NB*NHH*TT*DD];
__device__ float g_k[(size_t)NB*NHH*TT*DD];
__device__ float g_v[(size_t)NB*NHH*TT*DD];
__device__ float g_q0[(size_t)NB*HIDD];
__device__ int   g_gidx[(size_t)NB*NHH*(TT/4)];
__device__ int   g_lidx[(size_t)NB*NHH*(3*TT/4)];
// split planes — uint4-typed so bases are 16-byte aligned
__device__ uint4 g_Ahi4[(size_t)NB*TT*HIDD/8];   // A bf16 hi (K gemm)
__device__ uint4 g_Alo4[(size_t)NB*TT*HIDD/8];   // A bf16 lo
__device__ uint4 g_Afh4[(size_t)NB*TT*HIDD/8];   // A fp16 hi (Q,V gemm)
__device__ uint4 g_Afl4[(size_t)NB*TT*HIDD/8];   // A fp16 lo
__device__ uint4 g_Whi4[(size_t)HIDD*HIDD/8];    // Wk bf16 hi
__device__ uint4 g_Wlo4[(size_t)HIDD*HIDD/8];    // Wk bf16 lo
__device__ uint4 g_Wfh4[(size_t)2*HIDD*HIDD/8];  // Wq (slot0), Wv (slot1) fp16 hi

// ---------------- helpers ----------------
__device__ __forceinline__ unsigned short f2bf(float x)
{
    unsigned u = __float_as_uint(x);
    u += 0x7FFFu + ((u >> 16) & 1u);
    return (unsigned short)(u >> 16);
}
__device__ __forceinline__ float bf2f(unsigned short h)
{
    return __uint_as_float(((unsigned)h) << 16);
}

__device__ __forceinline__ void mma_bf16(float& d0, float& d1, float& d2, float& d3,
                                         unsigned a0, unsigned a1, unsigned a2, unsigned a3,
                                         unsigned b0, unsigned b1)
{
    asm volatile(
        "mma.sync.aligned.m16n8k16.row.col.f32.bf16.bf16.f32 "
        "{%0,%1,%2,%3}, {%4,%5,%6,%7}, {%8,%9}, {%0,%1,%2,%3};\n"
        : "+f"(d0), "+f"(d1), "+f"(d2), "+f"(d3)
        : "r"(a0), "r"(a1), "r"(a2), "r"(a3), "r"(b0), "r"(b1));
}
__device__ __forceinline__ void mma_f16(float& d0, float& d1, float& d2, float& d3,
                                        unsigned a0, unsigned a1, unsigned a2, unsigned a3,
                                        unsigned b0, unsigned b1)
{
    asm volatile(
        "mma.sync.aligned.m16n8k16.row.col.f32.f16.f16.f32 "
        "{%0,%1,%2,%3}, {%4,%5,%6,%7}, {%8,%9}, {%0,%1,%2,%3};\n"
        : "+f"(d0), "+f"(d1), "+f"(d2), "+f"(d3)
        : "r"(a0), "r"(a1), "r"(a2), "r"(a3), "r"(b0), "r"(b1));
}

__device__ __forceinline__ void ldsm4(unsigned& r0, unsigned& r1,
                                      unsigned& r2, unsigned& r3, unsigned saddr)
{
    asm volatile("ldmatrix.sync.aligned.m8n8.x4.shared.b16 {%0,%1,%2,%3}, [%4];"
                 : "=r"(r0), "=r"(r1), "=r"(r2), "=r"(r3) : "r"(saddr));
}

__device__ __forceinline__ void cp16(void* smem_dst, const void* gsrc)
{
    unsigned saddr = (unsigned)__cvta_generic_to_shared(smem_dst);
    asm volatile("cp.async.ca.shared.global [%0], [%1], 16;\n"
                 :: "r"(saddr), "l"(gsrc));
}
__device__ __forceinline__ void cp_commit()
{
    asm volatile("cp.async.commit_group;\n" ::: "memory");
}
template <int N> __device__ __forceinline__ void cp_wait()
{
    asm volatile("cp.async.wait_group %0;\n" :: "n"(N) : "memory");
}

// ---------------- conversions ------------------------------------------------------
__global__ void cvt_a_kernel(const float* __restrict__ in,
                             uint2* __restrict__ bh, uint2* __restrict__ bl,
                             uint2* __restrict__ fh, uint2* __restrict__ fl, int n4)
{
    int i = blockIdx.x * blockDim.x + threadIdx.x;
    if (i >= n4) return;
    float4 v = ((const float4*)in)[i];
    unsigned short h0 = f2bf(v.x), h1 = f2bf(v.y), h2 = f2bf(v.z), h3 = f2bf(v.w);
    unsigned short l0 = f2bf(v.x - bf2f(h0)), l1 = f2bf(v.y - bf2f(h1));
    unsigned short l2 = f2bf(v.z - bf2f(h2)), l3 = f2bf(v.w - bf2f(h3));
    bh[i] = make_uint2((unsigned)h0 | ((unsigned)h1 << 16),
                       (unsigned)h2 | ((unsigned)h3 << 16));
    bl[i] = make_uint2((unsigned)l0 | ((unsigned)l1 << 16),
                       (unsigned)l2 | ((unsigned)l3 << 16));
    __half fh0 = __float2half_rn(v.x), fh1 = __float2half_rn(v.y);
    __half fh2 = __float2half_rn(v.z), fh3 = __float2half_rn(v.w);
    __half fl0 = __float2half_rn(v.x - __half2float(fh0));
    __half fl1 = __float2half_rn(v.y - __half2float(fh1));
    __half fl2 = __float2half_rn(v.z - __half2float(fh2));
    __half fl3 = __float2half_rn(v.w - __half2float(fh3));
    fh[i] = make_uint2((unsigned)__half_as_ushort(fh0) | ((unsigned)__half_as_ushort(fh1) << 16),
                       (unsigned)__half_as_ushort(fh2) | ((unsigned)__half_as_ushort(fh3) << 16));
    fl[i] = make_uint2((unsigned)__half_as_ushort(fl0) | ((unsigned)__half_as_ushort(fl1) << 16),
                       (unsigned)__half_as_ushort(fl2) | ((unsigned)__half_as_ushort(fl3) << 16));
}

__global__ void cvt_w_kernel(const float* __restrict__ Wq,
                             const float* __restrict__ Wk,
                             const float* __restrict__ Wv,
                             uint2* __restrict__ bh, uint2* __restrict__ bl,
                             uint2* __restrict__ fh, int n4)
{
    int i = blockIdx.x * blockDim.x + threadIdx.x;
    if (i >= n4) return;
    int w = blockIdx.y;
    if (w == 1) {
        float4 v = ((const float4*)Wk)[i];
        unsigned short h0 = f2bf(v.x), h1 = f2bf(v.y), h2 = f2bf(v.z), h3 = f2bf(v.w);
        unsigned short l0 = f2bf(v.x - bf2f(h0)), l1 = f2bf(v.y - bf2f(h1));
        unsigned short l2 = f2bf(v.z - bf2f(h2)), l3 = f2bf(v.w - bf2f(h3));
        bh[i] = make_uint2((unsigned)h0 | ((unsigned)h1 << 16),
                           (unsigned)h2 | ((unsigned)h3 << 16));
        bl[i] = make_uint2((unsigned)l0 | ((unsigned)l1 << 16),
                           (unsigned)l2 | ((unsigned)l3 << 16));
    } else {
        const float* in = (w == 0) ? Wq : Wv;
        int slot = (w == 0) ? 0 : 1;
        float4 v = ((const float4*)in)[i];
        __half fh0 = __float2half_rn(v.x), fh1 = __float2half_rn(v.y);
        __half fh2 = __float2half_rn(v.z), fh3 = __float2half_rn(v.w);
        fh[(size_t)slot * n4 + i] =
            make_uint2((unsigned)__half_as_ushort(fh0) | ((unsigned)__half_as_ushort(fh1) << 16),
                       (unsigned)__half_as_ushort(fh2) | ((unsigned)__half_as_ushort(fh3) << 16));
    }
}

__global__ void q0_kernel(const float* __restrict__ hs,
                          const float* __restrict__ Wq,
                          const float* __restrict__ bq)
{
    const int c = blockIdx.x;
    const int n = blockIdx.y;
    const int tid = threadIdx.x;
    __shared__ float red[128];
    const float* xr = hs + (size_t)n * TT * HIDD;
    const float* wr = Wq + (size_t)c * HIDD;
    float pa = 0.0f;
    for (int k = tid; k < HIDD; k += 128) pa = fmaf(xr[k], wr[k], pa);
    red[tid] = pa;
    __syncthreads();
    for (int off = 64; off > 0; off >>= 1) {
        if (tid < off) red[tid] += red[tid + off];
        __syncthreads();
    }
    if (tid == 0) g_q0[(size_t)n * HIDD + c] = red[0] + bq[c];
}

// ============= fused QKV GEMM (one launch): z=0 Q, z=1 V (fp16 2-term), z=2 K =====
#define GSTR 20
#define PLW  (128 * GSTR)
#define PA_HI 0
#define PA_LO (1 * PLW)
#define PB_HI (2 * PLW)
#define PB_LO (3 * PLW)
#define STGW  (4 * PLW)               /* 40KB stage; QV uses 3 planes of it */

__global__ __launch_bounds__(256, 2)
void gemm_all_kernel(const float* __restrict__ bq,
                     const float* __restrict__ bk,
                     const float* __restrict__ bv,
                     float* __restrict__ oq,
                     float* __restrict__ ok,
                     float* __restrict__ ov)
{
    extern __shared__ unsigned gsm[];
    const int tid = threadIdx.x;
    const int m0 = blockIdx.y * 128;
    const int n0 = blockIdx.x * 128;
    const int z  = blockIdx.z;
    const bool isK = (z == 2);

    const char* Ah;
    const char* Al;
    const char* Bh;
    const char* Bl = nullptr;
    const float* bias;
    float* out;
    if (isK) {
        Ah = (const char*)((const __nv_bfloat16*)g_Ahi4 + (size_t)m0 * HIDD);
        Al = (const char*)((const __nv_bfloat16*)g_Alo4 + (size_t)m0 * HIDD);
        Bh = (const char*)((const __nv_bfloat16*)g_Whi4 + (size_t)n0 * HIDD);
        Bl = (const char*)((const __nv_bfloat16*)g_Wlo4 + (size_t)n0 * HIDD);
        bias = bk; out = ok;
    } else {
        Ah = (const char*)((const __half*)g_Afh4 + (size_t)m0 * HIDD);
        Al = (const char*)((const __half*)g_Afl4 + (size_t)m0 * HIDD);
        Bh = (const char*)((const __half*)g_Wfh4 + ((size_t)z * HIDD + n0) * HIDD);
        bias = z ? bv : bq;
        out = z ? ov : oq;
    }

    const int lane = tid & 31;
    const int warp = tid >> 5;
    const int wm = warp >> 1;
    const int wn = warp & 1;
    const int qr = lane >> 2;
    const int qc = lane & 3;
    const int rA = wm * 32;
    const int cB = wn * 64;

    const unsigned smem_base = (unsigned)__cvta_generic_to_shared(gsm);
    const int a_row = rA + (lane & 7) + ((lane >> 3) & 1) * 8;
    const unsigned a_k = ((lane >> 4) & 1) * 16;
    const int b_row = cB + (lane & 7) + ((lane >> 4) & 1) * 8;
    const unsigned b_k = ((lane >> 3) & 1) * 16;

    float acc[2][8][4];
#pragma unroll
    for (int mt = 0; mt < 2; mt++)
#pragma unroll
        for (int nt = 0; nt < 8; nt++)
#pragma unroll
            for (int e = 0; e < 4; e++) acc[mt][nt][e] = 0.0f;

    // ---- stage loader (planes depend on z) ----
    auto load_stage = [&](int buf, int kofs) {
        unsigned* st = gsm + buf * STGW;
#pragma unroll
        for (int i = 0; i < 2; i++) {
            int c = tid + i * 256;
            int row = c >> 2;
            int cw = c & 3;
            size_t go = ((size_t)row * HIDD + kofs + cw * 8) * 2;  // bytes
            unsigned* sp = st + row * GSTR + cw * 4;
            cp16(sp + PA_HI, Ah + go);
            cp16(sp + PA_LO, Al + go);
            cp16(sp + PB_HI, Bh + go);
            if (isK) cp16(sp + PB_LO, Bl + go);
        }
        cp_commit();
    };

    load_stage(0, 0);

    const int NIT = HIDD / 32;
    for (int it = 0; it < NIT; it++) {
        if (it + 1 < NIT) {
            load_stage((it + 1) & 1, (it + 1) * 32);
            cp_wait<1>();
        } else {
            cp_wait<0>();
        }
        __syncthreads();

        const unsigned sb = smem_base + ((it & 1) * STGW) * 4;
#pragma unroll
        for (int s = 0; s < 2; s++) {
            unsigned a_hi[2][4], a_lo[2][4];
#pragma unroll
            for (int mt = 0; mt < 2; mt++) {
                unsigned ao = (unsigned)(a_row + mt * 16) * 80 + s * 32 + a_k;
                ldsm4(a_hi[mt][0], a_hi[mt][1], a_hi[mt][2], a_hi[mt][3],
                      sb + PA_HI * 4 + ao);
                ldsm4(a_lo[mt][0], a_lo[mt][1], a_lo[mt][2], a_lo[mt][3],
                      sb + PA_LO * 4 + ao);
            }
#pragma unroll
            for (int p = 0; p < 4; p++) {
                unsigned bo = (unsigned)(b_row + p * 16) * 80 + s * 32 + b_k;
                unsigned bh0a, bh1a, bh0b, bh1b;
                ldsm4(bh0a, bh1a, bh0b, bh1b, sb + PB_HI * 4 + bo);
                if (isK) {
                    unsigned bl0a, bl1a, bl0b, bl1b;
                    ldsm4(bl0a, bl1a, bl0b, bl1b, sb + PB_LO * 4 + bo);
#pragma unroll
                    for (int mt = 0; mt < 2; mt++) {
                        float* c0 = acc[mt][2 * p];
                        mma_bf16(c0[0], c0[1], c0[2], c0[3],
                                 a_hi[mt][0], a_hi[mt][1], a_hi[mt][2], a_hi[mt][3], bh0a, bh1a);
                        mma_bf16(c0[0], c0[1], c0[2], c0[3],
                                 a_hi[mt][0], a_hi[mt][1], a_hi[mt][2], a_hi[mt][3], bl0a, bl1a);
                        mma_bf16(c0[0], c0[1], c0[2], c0[3],
                                 a_lo[mt][0], a_lo[mt][1], a_lo[mt][2], a_lo[mt][3], bh0a, bh1a);
                        float* c1 = acc[mt][2 * p + 1];
                        mma_bf16(c1[0], c1[1], c1[2], c1[3],
                                 a_hi[mt][0], a_hi[mt][1], a_hi[mt][2], a_hi[mt][3], bh0b, bh1b);
                        mma_bf16(c1[0], c1[1], c1[2], c1[3],
                                 a_hi[mt][0], a_hi[mt][1], a_hi[mt][2], a_hi[mt][3], bl0b, bl1b);
                        mma_bf16(c1[0], c1[1], c1[2], c1[3],
                                 a_lo[mt][0], a_lo[mt][1], a_lo[mt][2], a_lo[mt][3], bh0b, bh1b);
                    }
                } else {
#pragma unroll
                    for (int mt = 0; mt < 2; mt++) {
                        float* c0 = acc[mt][2 * p];
                        mma_f16(c0[0], c0[1], c0[2], c0[3],
                                a_hi[mt][0], a_hi[mt][1], a_hi[mt][2], a_hi[mt][3], bh0a, bh1a);
                        mma_f16(c0[0], c0[1], c0[2], c0[3],
                                a_lo[mt][0], a_lo[mt][1], a_lo[mt][2], a_lo[mt][3], bh0a, bh1a);
                        float* c1 = acc[mt][2 * p + 1];
                        mma_f16(c1[0], c1[1], c1[2], c1[3],
                                a_hi[mt][0], a_hi[mt][1], a_hi[mt][2], a_hi[mt][3], bh0b, bh1b);
                        mma_f16(c1[0], c1[1], c1[2], c1[3],
                                a_lo[mt][0], a_lo[mt][1], a_lo[mt][2], a_lo[mt][3], bh0b, bh1b);
                    }
                }
            }
        }
        __syncthreads();
    }

#pragma unroll
    for (int mt = 0; mt < 2; mt++) {
#pragma unroll
        for (int nt = 0; nt < 8; nt++) {
#pragma unroll
            for (int half = 0; half < 2; half++) {
                int row = m0 + rA + mt * 16 + qr + half * 8;
                int nb  = row >> 12;
                int t   = row & (TT - 1);
                int col = n0 + cB + nt * 8 + qc * 2;
                int h = col >> 6;
                int d = col & 63;
                float* op = out + (((size_t)(nb * NHH + h)) * TT + t) * DD + d;
                op[0] = acc[mt][nt][half * 2 + 0] + bias[col];
                op[1] = acc[mt][nt][half * 2 + 1] + bias[col + 1];
            }
        }
    }
}

// ---------------- top-k selection: 4 chunks per 256-thread block ------------------
__global__ void select_kernel(const float* __restrict__ mask,
                              const float* __restrict__ bq)
{
    const int sub = threadIdx.x >> 6;         // 0..3
    const int i   = threadIdx.x & 63;
    const int blk = blockIdx.x * 4 + sub;
    const int h   = blockIdx.y;
    const int n   = blockIdx.z;
    __shared__ float norms[4][64];
    __shared__ int flags[4][64];

    const int token = blk * 64 + i;
    const float* kr = g_k + (((size_t)(n * NHH + h)) * TT + token) * DD;
    const float* bqr = bq + h * DD;
    float s = 0.0f;
#pragma unroll
    for (int d = 0; d < DD; d++) { float vv = kr[d] + bqr[d]; s += vv * vv; }
    if (mask[n * TT + token] != 0.0f) s = 0.0f;
    norms[sub][i] = s;
    __syncthreads();

    float mine = norms[sub][i];
    int rank = 0;
    for (int j = 0; j < 64; j++) {
        float nj = norms[sub][j];
        rank += (nj < mine) || (nj == mine && j < i);
    }
    int top = (rank >= 64 - TOPKK) ? 1 : 0;
    flags[sub][i] = top;
    __syncthreads();

    int pos = 0;
    for (int j = 0; j < i; j++) pos += flags[sub][j];
    if (top)
        g_gidx[((size_t)(n * NHH + h)) * (TT / 4) + blk * TOPKK + pos] = token;
    else
        g_lidx[((size_t)(n * NHH + h)) * (3 * TT / 4) + blk * 48 + (i - pos)] = token;
}

// ======== fused local+global flash (tf32) — the merge IS online softmax ===========
#define KC     112
#define NCHK   3
#define QSTRW  68
#define VSTRW  72
#define QS_OFF 0
#define KS_OFF (QS_OFF + 128*QSTRW)
#define VS_OFF (KS_OFF + KC*QSTRW)
#define MS_OFF (VS_OFF + KC*VSTRW)
#define LSMEM_WORDS (MS_OFF + KC)

__device__ __forceinline__ float to_tf32(float x)
{
    float r;
    asm("cvt.rna.tf32.f32 %0, %1;" : "=f"(r) : "f"(x));
    return r;
}

__device__ __forceinline__ void mma_tf32(float& d0, float& d1, float& d2, float& d3,
                                         float a0, float a1, float a2, float a3,
                                         float b0, float b1)
{
    asm volatile(
        "mma.sync.aligned.m16n8k8.row.col.f32.tf32.tf32.f32 "
        "{%0,%1,%2,%3}, {%4,%5,%6,%7}, {%8,%9}, {%0,%1,%2,%3};\n"
        : "+f"(d0), "+f"(d1), "+f"(d2), "+f"(d3)
        : "r"(__float_as_uint(a0)), "r"(__float_as_uint(a1)),
          "r"(__float_as_uint(a2)), "r"(__float_as_uint(a3)),
          "r"(__float_as_uint(b0)), "r"(__float_as_uint(b1)));
}

__global__ __launch_bounds__(256, 2)
void attn_fused_kernel(const float* __restrict__ mask,
                       float* __restrict__ out)
{
    extern __shared__ float sm[];
    float* Qs = sm + QS_OFF;
    float* Ks = sm + KS_OFF;
    float* Vs = sm + VS_OFF;
    float* Ms = sm + MS_OFF;

    const int qb = blockIdx.x;
    const int h  = blockIdx.y;
    const int n  = blockIdx.z;
    const int tid = threadIdx.x;
    const int lane = tid & 31;
    const int warp = tid >> 5;
    const int qr = lane >> 2;
    const int qc = lane & 3;
    const int w16 = warp * 16;

    const size_t ho = (size_t)(n * NHH + h);
    const float* kb = g_k + ho * TT * DD;
    const float* vb = g_v + ho * TT * DD;
    const int* lix = g_lidx + ho * (3 * TT / 4);
    const int* gix = g_gidx + ho * (TT / 4);

#pragma unroll
    for (int i = 0; i < 8; i++) {
        int idx = tid + i * 256;
        int r = idx >> 4, c4 = idx & 15;
        const float4 qv = *(const float4*)(g_q + (ho * TT + qb * 128 + r) * DD + c4 * 4);
        float* dst = Qs + r * QSTRW + c4 * 4;
        dst[0] = to_tf32(qv.x); dst[1] = to_tf32(qv.y);
        dst[2] = to_tf32(qv.z); dst[3] = to_tf32(qv.w);
    }

    float m0 = -1e30f, m1 = -1e30f, l0 = 0.0f, l1 = 0.0f;
    float o[8][4];
#pragma unroll
    for (int nt = 0; nt < 8; nt++)
#pragma unroll
        for (int e = 0; e < 4; e++) o[nt][e] = 0.0f;

    const int src0 = (qr << 2) + (qc >> 1);
    const int src2 = src0 + 2;
    const bool odd = (qc & 1) != 0;

    // ---- 3 local chunks + 1 global chunk (same online-softmax state) ----
    for (int ch = 0; ch < NCHK + 1; ch++) {
        const bool glob = (ch == NCHK);
        __syncthreads();
        if (!glob) {
            for (int idx = tid; idx < KC * 16; idx += 256) {
                int r = idx >> 4, c4 = idx & 15;
                int kk = ch * KC + r;
                float4 kv = make_float4(0.f, 0.f, 0.f, 0.f);
                float4 vv = make_float4(0.f, 0.f, 0.f, 0.f);
                float mval = -1e30f;
                if (kk < 288) {
                    int g = qb * 96 - 96 + kk;
                    if (g >= 0 && g < 3 * TT / 4) {
                        int src = lix[g];
                        kv = *(const float4*)(kb + (size_t)src * DD + c4 * 4);
                        vv = *(const float4*)(vb + (size_t)src * DD + c4 * 4);
                        mval = mask[n * TT + src];
                    } else {
                        mval = NEGV;
                    }
                } else if (kk == 288) {
                    kv = *(const float4*)(kb + c4 * 4);
                    vv = *(const float4*)(vb + c4 * 4);
                    mval = 0.0f;
                }
                float* kd = Ks + r * QSTRW + c4 * 4;
                kd[0] = to_tf32(kv.x); kd[1] = to_tf32(kv.y);
                kd[2] = to_tf32(kv.z); kd[3] = to_tf32(kv.w);
                float* vd = Vs + r * VSTRW + c4 * 4;
                vd[0] = to_tf32(vv.x); vd[1] = to_tf32(vv.y);
                vd[2] = to_tf32(vv.z); vd[3] = to_tf32(vv.w);
                if (c4 == 0) Ms[r] = mval;
            }
        } else {
            // global chunk: rows 0-47 = sel-chunk 2qb (window prev/cur/next of 16),
            // rows 48-95 = sel-chunk 2qb+1
            for (int idx = tid; idx < 96 * 16; idx += 256) {
                int r = idx >> 4, c4 = idx & 15;
                int half = (r >= 48);
                int g = (2 * qb - 1 + half) * 16 + (r - half * 48);
                float4 kv = make_float4(0.f, 0.f, 0.f, 0.f);
                float4 vv = make_float4(0.f, 0.f, 0.f, 0.f);
                float mval = NEGV;
                if (g >= 0 && g < TT / 4) {
                    int src = gix[g];
                    kv = *(const float4*)(kb + (size_t)src * DD + c4 * 4);
                    vv = *(const float4*)(vb + (size_t)src * DD + c4 * 4);
                    mval = mask[n * TT + src];
                }
                float* kd = Ks + r * QSTRW + c4 * 4;
                kd[0] = to_tf32(kv.x); kd[1] = to_tf32(kv.y);
                kd[2] = to_tf32(kv.z); kd[3] = to_tf32(kv.w);
                float* vd = Vs + r * VSTRW + c4 * 4;
                vd[0] = to_tf32(vv.x); vd[1] = to_tf32(vv.y);
                vd[2] = to_tf32(vv.z); vd[3] = to_tf32(vv.w);
                if (c4 == 0) Ms[r] = mval;
            }
        }
        __syncthreads();

        const int NT = glob ? 6 : 14;
        const int rb = glob ? ((warp >= 4) ? 48 : 0) : 0;

        float s[14][4];
        for (int nt = 0; nt < NT; nt++)
#pragma unroll
            for (int e = 0; e < 4; e++) s[nt][e] = 0.0f;

#pragma unroll
        for (int k8 = 0; k8 < 8; k8++) {
            const int kc0 = k8 * 8 + qc;
            float a0 = Qs[(w16 + qr) * QSTRW + kc0];
            float a1 = Qs[(w16 + qr + 8) * QSTRW + kc0];
            float a2 = Qs[(w16 + qr) * QSTRW + kc0 + 4];
            float a3 = Qs[(w16 + qr + 8) * QSTRW + kc0 + 4];
            for (int nt = 0; nt < NT; nt++) {
                float b0 = Ks[(rb + nt * 8 + qr) * QSTRW + kc0];
                float b1 = Ks[(rb + nt * 8 + qr) * QSTRW + kc0 + 4];
                mma_tf32(s[nt][0], s[nt][1], s[nt][2], s[nt][3],
                         a0, a1, a2, a3, b0, b1);
            }
        }

        float cmax0 = -1e30f, cmax1 = -1e30f;
        for (int nt = 0; nt < NT; nt++) {
            float mc0 = Ms[rb + nt * 8 + 2 * qc];
            float mc1 = Ms[rb + nt * 8 + 2 * qc + 1];
            s[nt][0] = s[nt][0] * 0.125f + mc0;
            s[nt][1] = s[nt][1] * 0.125f + mc1;
            s[nt][2] = s[nt][2] * 0.125f + mc0;
            s[nt][3] = s[nt][3] * 0.125f + mc1;
            cmax0 = fmaxf(cmax0, fmaxf(s[nt][0], s[nt][1]));
            cmax1 = fmaxf(cmax1, fmaxf(s[nt][2], s[nt][3]));
        }
        cmax0 = fmaxf(cmax0, __shfl_xor_sync(0xffffffffu, cmax0, 1));
        cmax0 = fmaxf(cmax0, __shfl_xor_sync(0xffffffffu, cmax0, 2));
        cmax1 = fmaxf(cmax1, __shfl_xor_sync(0xffffffffu, cmax1, 1));
        cmax1 = fmaxf(cmax1, __shfl_xor_sync(0xffffffffu, cmax1, 2));

        float mn0 = fmaxf(m0, cmax0);
        float mn1 = fmaxf(m1, cmax1);
        float corr0 = __expf(m0 - mn0);
        float corr1 = __expf(m1 - mn1);
        m0 = mn0; m1 = mn1;

        float rs0 = 0.0f, rs1 = 0.0f;
        for (int nt = 0; nt < NT; nt++) {
            float p0 = __expf(s[nt][0] - mn0);
            float p1 = __expf(s[nt][1] - mn0);
            float p2 = __expf(s[nt][2] - mn1);
            float p3 = __expf(s[nt][3] - mn1);
            rs0 += p0 + p1; rs1 += p2 + p3;
            s[nt][0] = to_tf32(p0); s[nt][1] = to_tf32(p1);
            s[nt][2] = to_tf32(p2); s[nt][3] = to_tf32(p3);
        }
        rs0 += __shfl_xor_sync(0xffffffffu, rs0, 1);
        rs0 += __shfl_xor_sync(0xffffffffu, rs0, 2);
        rs1 += __shfl_xor_sync(0xffffffffu, rs1, 1);
        rs1 += __shfl_xor_sync(0xffffffffu, rs1, 2);
        l0 = l0 * corr0 + rs0;
        l1 = l1 * corr1 + rs1;

#pragma unroll
        for (int nt = 0; nt < 8; nt++) {
            o[nt][0] *= corr0; o[nt][1] *= corr0;
            o[nt][2] *= corr1; o[nt][3] *= corr1;
        }

        for (int kt = 0; kt < NT; kt++) {
            float p0 = s[kt][0], p1 = s[kt][1], p2 = s[kt][2], p3 = s[kt][3];
            float t0 = __shfl_sync(0xffffffffu, p0, src0);
            float t1 = __shfl_sync(0xffffffffu, p1, src0);
            float t2 = __shfl_sync(0xffffffffu, p2, src0);
            float t3 = __shfl_sync(0xffffffffu, p3, src0);
            float u0 = __shfl_sync(0xffffffffu, p0, src2);
            float u1 = __shfl_sync(0xffffffffu, p1, src2);
            float u2 = __shfl_sync(0xffffffffu, p2, src2);
            float u3 = __shfl_sync(0xffffffffu, p3, src2);
            float a0 = odd ? t1 : t0;
            float a1 = odd ? t3 : t2;
            float a2 = odd ? u1 : u0;
            float a3 = odd ? u3 : u2;
#pragma unroll
            for (int nt = 0; nt < 8; nt++) {
                float b0 = Vs[(rb + kt * 8 + qc) * VSTRW + nt * 8 + qr];
                float b1 = Vs[(rb + kt * 8 + qc + 4) * VSTRW + nt * 8 + qr];
                mma_tf32(o[nt][0], o[nt][1], o[nt][2], o[nt][3],
                         a0, a1, a2, a3, b0, b1);
            }
        }
    }

    // ---- epilogue: ctx = O / l (merge already folded into the online softmax) ----
    float inv0 = 1.0f / l0;
    float inv1 = 1.0f / l1;
    int row0 = qb * 128 + w16 + qr;
    int row1 = row0 + 8;
    float* op0 = out + ((size_t)n * TT + row0) * HIDD + h * DD;
    float* op1 = out + ((size_t)n * TT + row1) * HIDD + h * DD;
#pragma unroll
    for (int nt = 0; nt < 8; nt++) {
        int c0 = nt * 8 + 2 * qc;
#pragma unroll
        for (int e = 0; e < 2; e++) {
            op0[c0 + e] = o[nt][e] * inv0;
            op1[c0 + e] = o[nt][2 + e] * inv1;
        }
    }
}

// ---------------- BOS row (exact q from g_q0) --------------------------------------
__global__ void bos_kernel(const float* __restrict__ mask,
                           float* __restrict__ out)
{
    const int h = blockIdx.x;
    const int n = blockIdx.y;
    const int tid = threadIdx.x;
    __shared__ float sc[TT];
    __shared__ float qs[64];
    __shared__ float red[128];

    const size_t ho = (size_t)(n * NHH + h);
    const float* kb = g_k + ho * TT * DD;
    const float* vb = g_v + ho * TT * DD;
    if (tid < 64) qs[tid] = g_q0[(size_t)n * HIDD + h * DD + tid];
    __syncthreads();

    float lmax = -1e30f;
    for (int t = tid; t < TT; t += 128) {
        const float* kr = kb + (size_t)t * DD;
        float dot = 0.0f;
#pragma unroll
        for (int d = 0; d < 64; d++) dot = fmaf(qs[d], kr[d], dot);
        float s = dot + mask[n * TT + t];
        sc[t] = s;
        lmax = fmaxf(lmax, s);
    }
    red[tid] = lmax;
    __syncthreads();
    for (int off = 64; off > 0; off >>= 1) {
        if (tid < off) red[tid] = fmaxf(red[tid], red[tid + off]);
        __syncthreads();
    }
    float mmax = red[0];
    float lsum = 0.0f;
    for (int t = tid; t < TT; t += 128) {
        float p = __expf(sc[t] - mmax);
        sc[t] = p;
        lsum += p;
    }
    __syncthreads();
    red[tid] = lsum;
    __syncthreads();
    for (int off = 64; off > 0; off >>= 1) {
        if (tid < off) red[tid] += red[tid + off];
        __syncthreads();
    }
    float inv = 1.0f / red[0];
    __syncthreads();
    // PV split over 128 threads: (half, d) each sums 2048 keys
    {
        int half = tid >> 6;
        int d = tid & 63;
        float acc = 0.0f;
        int t0 = half * (TT / 2);
        for (int t = t0; t < t0 + TT / 2; t++)
            acc = fmaf(sc[t], vb[(size_t)t * DD + d], acc);
        red[tid] = acc;
    }
    __syncthreads();
    if (tid < 64)
        out[((size_t)n * TT) * HIDD + h * DD + tid] =
            (red[tid] + red[tid + 64]) * inv;
}

// ---------------- launch ----------------------------------------------------------
extern "C" void kernel_launch(void* const* d_in, const int* in_sizes, int n_in,
                              void* d_out, int out_size)
{
    (void)in_sizes; (void)n_in; (void)out_size;
    const float* hs   = (const float*)d_in[0];
    const float* mask = (const float*)d_in[1];
    const float* Wq   = (const float*)d_in[2];
    const float* bq   = (const float*)d_in[3];
    const float* Wk   = (const float*)d_in[4];
    const float* bk   = (const float*)d_in[5];
    const float* Wv   = (const float*)d_in[6];
    const float* bv   = (const float*)d_in[7];
    float* out = (float*)d_out;

    float *qp, *kp, *vp;
    cudaGetSymbolAddress((void**)&qp, g_q);
    cudaGetSymbolAddress((void**)&kp, g_k);
    cudaGetSymbolAddress((void**)&vp, g_v);
    uint2 *ahp, *alp, *afh, *afl, *whp, *wlp, *wfh;
    cudaGetSymbolAddress((void**)&ahp, g_Ahi4);
    cudaGetSymbolAddress((void**)&alp, g_Alo4);
    cudaGetSymbolAddress((void**)&afh, g_Afh4);
    cudaGetSymbolAddress((void**)&afl, g_Afl4);
    cudaGetSymbolAddress((void**)&whp, g_Whi4);
    cudaGetSymbolAddress((void**)&wlp, g_Wlo4);
    cudaGetSymbolAddress((void**)&wfh, g_Wfh4);

    {
        int n4a = NB * TT * HIDD / 4;
        cvt_a_kernel<<<(n4a + 255) / 256, 256>>>(hs, ahp, alp, afh, afl, n4a);
        int n4w = HIDD * HIDD / 4;
        cvt_w_kernel<<<dim3((n4w + 255) / 256, 3), 256>>>(Wq, Wk, Wv, whp, wlp, wfh, n4w);
        q0_kernel<<<dim3(HIDD, NB), 128>>>(hs, Wq, bq);
    }

    {
        size_t gsmemb = (size_t)(2 * STGW) * sizeof(unsigned);   // 80 KB
        cudaFuncSetAttribute(gemm_all_kernel,
                             cudaFuncAttributeMaxDynamicSharedMemorySize, (int)gsmemb);
        gemm_all_kernel<<<dim3(HIDD / 128, (NB * TT) / 128, 3), 256, gsmemb>>>(
            bq, bk, bv, qp, kp, vp);
    }

    select_kernel<<<dim3(TT / 256, NHH, NB), 256>>>(mask, bq);

    size_t lsmem = (size_t)LSMEM_WORDS * sizeof(float);          // ~98 KB
    cudaFuncSetAttribute(attn_fused_kernel,
                         cudaFuncAttributeMaxDynamicSharedMemorySize, (int)lsmem);
    attn_fused_kernel<<<dim3(TT / 128, NHH, NB), 256, lsmem>>>(mask, out);

    bos_kernel<<<dim3(NHH, NB), 128>>>(mask, out);
}

// round 11
// speedup vs baseline: 1.2986x; 1.2986x over previous
#include <cuda_runtime.h>
#include <cuda_bf16.h>
#include <cuda_fp16.h>
#include <math.h>

#define NB   2
#define TT   4096
#define HIDD 1024
#define NHH  16
#define DD   64
#define TOPKK 16
#define NEGV (-10000.0f)

// ---------------- device scratch ----------------
__device__ float g_q[(size_t)NB*NHH*TT*DD];
__device__ float g_k[(size_t)NB*NHH*TT*DD];
__device__ float g_v[(size_t)NB*NHH*TT*DD];
__device__ float g_q0[(size_t)NB*HIDD];
__device__ int   g_gidx[(size_t)NB*NHH*(TT/4)];
__device__ int   g_lidx[(size_t)NB*NHH*(3*TT/4)];
__device__ uint4 g_Ahi4[(size_t)NB*TT*HIDD/8];
__device__ uint4 g_Alo4[(size_t)NB*TT*HIDD/8];
__device__ uint4 g_Afh4[(size_t)NB*TT*HIDD/8];
__device__ uint4 g_Afl4[(size_t)NB*TT*HIDD/8];
__device__ uint4 g_Whi4[(size_t)HIDD*HIDD/8];
__device__ uint4 g_Wlo4[(size_t)HIDD*HIDD/8];
__device__ uint4 g_Wfh4[(size_t)2*HIDD*HIDD/8];

// ---------------- helpers ----------------
__device__ __forceinline__ unsigned short f2bf(float x)
{
    unsigned u = __float_as_uint(x);
    u += 0x7FFFu + ((u >> 16) & 1u);
    return (unsigned short)(u >> 16);
}
__device__ __forceinline__ float bf2f(unsigned short h)
{
    return __uint_as_float(((unsigned)h) << 16);
}

__device__ __forceinline__ void mma_bf16(float& d0, float& d1, float& d2, float& d3,
                                         unsigned a0, unsigned a1, unsigned a2, unsigned a3,
                                         unsigned b0, unsigned b1)
{
    asm volatile(
        "mma.sync.aligned.m16n8k16.row.col.f32.bf16.bf16.f32 "
        "{%0,%1,%2,%3}, {%4,%5,%6,%7}, {%8,%9}, {%0,%1,%2,%3};\n"
        : "+f"(d0), "+f"(d1), "+f"(d2), "+f"(d3)
        : "r"(a0), "r"(a1), "r"(a2), "r"(a3), "r"(b0), "r"(b1));
}
__device__ __forceinline__ void mma_f16(float& d0, float& d1, float& d2, float& d3,
                                        unsigned a0, unsigned a1, unsigned a2, unsigned a3,
                                        unsigned b0, unsigned b1)
{
    asm volatile(
        "mma.sync.aligned.m16n8k16.row.col.f32.f16.f16.f32 "
        "{%0,%1,%2,%3}, {%4,%5,%6,%7}, {%8,%9}, {%0,%1,%2,%3};\n"
        : "+f"(d0), "+f"(d1), "+f"(d2), "+f"(d3)
        : "r"(a0), "r"(a1), "r"(a2), "r"(a3), "r"(b0), "r"(b1));
}

__device__ __forceinline__ void ldsm4(unsigned& r0, unsigned& r1,
                                      unsigned& r2, unsigned& r3, unsigned saddr)
{
    asm volatile("ldmatrix.sync.aligned.m8n8.x4.shared.b16 {%0,%1,%2,%3}, [%4];"
                 : "=r"(r0), "=r"(r1), "=r"(r2), "=r"(r3) : "r"(saddr));
}

__device__ __forceinline__ void cp16(void* smem_dst, const void* gsrc)
{
    unsigned saddr = (unsigned)__cvta_generic_to_shared(smem_dst);
    asm volatile("cp.async.ca.shared.global [%0], [%1], 16;\n"
                 :: "r"(saddr), "l"(gsrc));
}
__device__ __forceinline__ void cp_commit()
{
    asm volatile("cp.async.commit_group;\n" ::: "memory");
}
template <int N> __device__ __forceinline__ void cp_wait()
{
    asm volatile("cp.async.wait_group %0;\n" :: "n"(N) : "memory");
}

// ---------------- conversions ------------------------------------------------------
__global__ void cvt_a_kernel(const float* __restrict__ in,
                             uint2* __restrict__ bh, uint2* __restrict__ bl,
                             uint2* __restrict__ fh, uint2* __restrict__ fl, int n4)
{
    int i = blockIdx.x * blockDim.x + threadIdx.x;
    if (i >= n4) return;
    float4 v = ((const float4*)in)[i];
    unsigned short h0 = f2bf(v.x), h1 = f2bf(v.y), h2 = f2bf(v.z), h3 = f2bf(v.w);
    unsigned short l0 = f2bf(v.x - bf2f(h0)), l1 = f2bf(v.y - bf2f(h1));
    unsigned short l2 = f2bf(v.z - bf2f(h2)), l3 = f2bf(v.w - bf2f(h3));
    bh[i] = make_uint2((unsigned)h0 | ((unsigned)h1 << 16),
                       (unsigned)h2 | ((unsigned)h3 << 16));
    bl[i] = make_uint2((unsigned)l0 | ((unsigned)l1 << 16),
                       (unsigned)l2 | ((unsigned)l3 << 16));
    __half fh0 = __float2half_rn(v.x), fh1 = __float2half_rn(v.y);
    __half fh2 = __float2half_rn(v.z), fh3 = __float2half_rn(v.w);
    __half fl0 = __float2half_rn(v.x - __half2float(fh0));
    __half fl1 = __float2half_rn(v.y - __half2float(fh1));
    __half fl2 = __float2half_rn(v.z - __half2float(fh2));
    __half fl3 = __float2half_rn(v.w - __half2float(fh3));
    fh[i] = make_uint2((unsigned)__half_as_ushort(fh0) | ((unsigned)__half_as_ushort(fh1) << 16),
                       (unsigned)__half_as_ushort(fh2) | ((unsigned)__half_as_ushort(fh3) << 16));
    fl[i] = make_uint2((unsigned)__half_as_ushort(fl0) | ((unsigned)__half_as_ushort(fl1) << 16),
                       (unsigned)__half_as_ushort(fl2) | ((unsigned)__half_as_ushort(fl3) << 16));
}

__global__ void cvt_w_kernel(const float* __restrict__ Wq,
                             const float* __restrict__ Wk,
                             const float* __restrict__ Wv,
                             uint2* __restrict__ bh, uint2* __restrict__ bl,
                             uint2* __restrict__ fh, int n4)
{
    int i = blockIdx.x * blockDim.x + threadIdx.x;
    if (i >= n4) return;
    int w = blockIdx.y;
    if (w == 1) {
        float4 v = ((const float4*)Wk)[i];
        unsigned short h0 = f2bf(v.x), h1 = f2bf(v.y), h2 = f2bf(v.z), h3 = f2bf(v.w);
        unsigned short l0 = f2bf(v.x - bf2f(h0)), l1 = f2bf(v.y - bf2f(h1));
        unsigned short l2 = f2bf(v.z - bf2f(h2)), l3 = f2bf(v.w - bf2f(h3));
        bh[i] = make_uint2((unsigned)h0 | ((unsigned)h1 << 16),
                           (unsigned)h2 | ((unsigned)h3 << 16));
        bl[i] = make_uint2((unsigned)l0 | ((unsigned)l1 << 16),
                           (unsigned)l2 | ((unsigned)l3 << 16));
    } else {
        const float* in = (w == 0) ? Wq : Wv;
        int slot = (w == 0) ? 0 : 1;
        float4 v = ((const float4*)in)[i];
        __half fh0 = __float2half_rn(v.x), fh1 = __float2half_rn(v.y);
        __half fh2 = __float2half_rn(v.z), fh3 = __float2half_rn(v.w);
        fh[(size_t)slot * n4 + i] =
            make_uint2((unsigned)__half_as_ushort(fh0) | ((unsigned)__half_as_ushort(fh1) << 16),
                       (unsigned)__half_as_ushort(fh2) | ((unsigned)__half_as_ushort(fh3) << 16));
    }
}

__global__ void q0_kernel(const float* __restrict__ hs,
                          const float* __restrict__ Wq,
                          const float* __restrict__ bq)
{
    const int c = blockIdx.x;
    const int n = blockIdx.y;
    const int tid = threadIdx.x;
    __shared__ float red[128];
    const float* xr = hs + (size_t)n * TT * HIDD;
    const float* wr = Wq + (size_t)c * HIDD;
    float pa = 0.0f;
    for (int k = tid; k < HIDD; k += 128) pa = fmaf(xr[k], wr[k], pa);
    red[tid] = pa;
    __syncthreads();
    for (int off = 64; off > 0; off >>= 1) {
        if (tid < off) red[tid] += red[tid + off];
        __syncthreads();
    }
    if (tid == 0) g_q0[(size_t)n * HIDD + c] = red[0] + bq[c];
}

// ============= fused QKV GEMM: swizzled 64B rows, 3-stage single-sync pipeline =====
// z=0 Q, z=1 V (fp16 2-term), z=2 K (bf16 3-term). Tile 128x128x32.
// smem row = 64B (16 words), swizzle: phys_chunk = chunk ^ ((row>>1)&3).
#define KSTR 16                        /* words per row */
#define PLW  (128 * KSTR)              /* 2048 words per plane (8KB) */
#define PA_HI 0
#define PA_LO (1 * PLW)
#define PB_HI (2 * PLW)
#define PB_LO (3 * PLW)
#define STGW  (4 * PLW)                /* 8192 words = 32KB per stage */
#define GSMEMB (3 * STGW * 4)          /* 96KB */

__global__ __launch_bounds__(256, 2)
void gemm_all_kernel(const float* __restrict__ bq,
                     const float* __restrict__ bk,
                     const float* __restrict__ bv,
                     float* __restrict__ oq,
                     float* __restrict__ ok,
                     float* __restrict__ ov)
{
    extern __shared__ unsigned gsm[];
    const int tid = threadIdx.x;
    const int m0 = blockIdx.y * 128;
    const int n0 = blockIdx.x * 128;
    const int z  = blockIdx.z;
    const bool isK = (z == 2);

    const char* Ah;
    const char* Al;
    const char* Bh;
    const char* Bl = nullptr;
    const float* bias;
    float* out;
    if (isK) {
        Ah = (const char*)((const __nv_bfloat16*)g_Ahi4 + (size_t)m0 * HIDD);
        Al = (const char*)((const __nv_bfloat16*)g_Alo4 + (size_t)m0 * HIDD);
        Bh = (const char*)((const __nv_bfloat16*)g_Whi4 + (size_t)n0 * HIDD);
        Bl = (const char*)((const __nv_bfloat16*)g_Wlo4 + (size_t)n0 * HIDD);
        bias = bk; out = ok;
    } else {
        Ah = (const char*)((const __half*)g_Afh4 + (size_t)m0 * HIDD);
        Al = (const char*)((const __half*)g_Afl4 + (size_t)m0 * HIDD);
        Bh = (const char*)((const __half*)g_Wfh4 + ((size_t)z * HIDD + n0) * HIDD);
        bias = z ? bv : bq;
        out = z ? ov : oq;
    }

    const int lane = tid & 31;
    const int warp = tid >> 5;
    const int wm = warp >> 1;
    const int wn = warp & 1;
    const int qr = lane >> 2;
    const int qc = lane & 3;
    const int rA = wm * 32;
    const int cB = wn * 64;

    const unsigned smem_base = (unsigned)__cvta_generic_to_shared(gsm);
    // ldmatrix per-thread row and k-chunk-bit
    const int a_r0 = rA + (lane & 7) + ((lane >> 3) & 1) * 8;
    const unsigned a_kbit = (lane >> 4) & 1;
    const int b_r0 = cB + (lane & 7) + ((lane >> 4) & 1) * 8;
    const unsigned b_kbit = (lane >> 3) & 1;

    float acc[2][8][4];
#pragma unroll
    for (int mt = 0; mt < 2; mt++)
#pragma unroll
        for (int nt = 0; nt < 8; nt++)
#pragma unroll
            for (int e = 0; e < 4; e++) acc[mt][nt][e] = 0.0f;

    // stage loader: 512 16B-chunks per plane, swizzled placement
    auto load_stage = [&](int buf, int kofs) {
        unsigned* st = gsm + buf * STGW;
#pragma unroll
        for (int i = 0; i < 2; i++) {
            int c = tid + i * 256;
            int row = c >> 2;
            int cw = c & 3;
            size_t go = ((size_t)row * HIDD + kofs + cw * 8) * 2;   // bytes
            int pw = (cw ^ ((row >> 1) & 3)) * 4;                   // phys chunk (words)
            unsigned* sp = st + row * KSTR + pw;
            cp16(sp + PA_HI, Ah + go);
            cp16(sp + PA_LO, Al + go);
            cp16(sp + PB_HI, Bh + go);
            if (isK) cp16(sp + PB_LO, Bl + go);
        }
        cp_commit();
    };

    load_stage(0, 0);
    load_stage(1, 32);

    const int NIT = HIDD / 32;       // 32
    int cur = 0;
    for (int it = 0; it < NIT; it++) {
        if (it + 1 < NIT) cp_wait<1>(); else cp_wait<0>();
        __syncthreads();
        if (it + 2 < NIT) {
            int s2 = cur + 2; if (s2 >= 3) s2 -= 3;
            load_stage(s2, (it + 2) * 32);
        }

        const unsigned sb = smem_base + cur * (STGW * 4);
#pragma unroll
        for (int s = 0; s < 2; s++) {
            unsigned a_hi[2][4], a_lo[2][4];
#pragma unroll
            for (int mt = 0; mt < 2; mt++) {
                int row = a_r0 + mt * 16;
                unsigned kc = (unsigned)s * 2 + a_kbit;
                unsigned ao = (unsigned)row * 64 + ((kc ^ ((unsigned)(row >> 1) & 3u)) << 4);
                ldsm4(a_hi[mt][0], a_hi[mt][1], a_hi[mt][2], a_hi[mt][3],
                      sb + PA_HI * 4 + ao);
                ldsm4(a_lo[mt][0], a_lo[mt][1], a_lo[mt][2], a_lo[mt][3],
                      sb + PA_LO * 4 + ao);
            }
#pragma unroll
            for (int p = 0; p < 4; p++) {
                int row = b_r0 + p * 16;
                unsigned kc = (unsigned)s * 2 + b_kbit;
                unsigned bo = (unsigned)row * 64 + ((kc ^ ((unsigned)(row >> 1) & 3u)) << 4);
                unsigned bh0a, bh1a, bh0b, bh1b;
                ldsm4(bh0a, bh1a, bh0b, bh1b, sb + PB_HI * 4 + bo);
                if (isK) {
                    unsigned bl0a, bl1a, bl0b, bl1b;
                    ldsm4(bl0a, bl1a, bl0b, bl1b, sb + PB_LO * 4 + bo);
#pragma unroll
                    for (int mt = 0; mt < 2; mt++) {
                        float* c0 = acc[mt][2 * p];
                        mma_bf16(c0[0], c0[1], c0[2], c0[3],
                                 a_hi[mt][0], a_hi[mt][1], a_hi[mt][2], a_hi[mt][3], bh0a, bh1a);
                        mma_bf16(c0[0], c0[1], c0[2], c0[3],
                                 a_hi[mt][0], a_hi[mt][1], a_hi[mt][2], a_hi[mt][3], bl0a, bl1a);
                        mma_bf16(c0[0], c0[1], c0[2], c0[3],
                                 a_lo[mt][0], a_lo[mt][1], a_lo[mt][2], a_lo[mt][3], bh0a, bh1a);
                        float* c1 = acc[mt][2 * p + 1];
                        mma_bf16(c1[0], c1[1], c1[2], c1[3],
                                 a_hi[mt][0], a_hi[mt][1], a_hi[mt][2], a_hi[mt][3], bh0b, bh1b);
                        mma_bf16(c1[0], c1[1], c1[2], c1[3],
                                 a_hi[mt][0], a_hi[mt][1], a_hi[mt][2], a_hi[mt][3], bl0b, bl1b);
                        mma_bf16(c1[0], c1[1], c1[2], c1[3],
                                 a_lo[mt][0], a_lo[mt][1], a_lo[mt][2], a_lo[mt][3], bh0b, bh1b);
                    }
                } else {
#pragma unroll
                    for (int mt = 0; mt < 2; mt++) {
                        float* c0 = acc[mt][2 * p];
                        mma_f16(c0[0], c0[1], c0[2], c0[3],
                                a_hi[mt][0], a_hi[mt][1], a_hi[mt][2], a_hi[mt][3], bh0a, bh1a);
                        mma_f16(c0[0], c0[1], c0[2], c0[3],
                                a_lo[mt][0], a_lo[mt][1], a_lo[mt][2], a_lo[mt][3], bh0a, bh1a);
                        float* c1 = acc[mt][2 * p + 1];
                        mma_f16(c1[0], c1[1], c1[2], c1[3],
                                a_hi[mt][0], a_hi[mt][1], a_hi[mt][2], a_hi[mt][3], bh0b, bh1b);
                        mma_f16(c1[0], c1[1], c1[2], c1[3],
                                a_lo[mt][0], a_lo[mt][1], a_lo[mt][2], a_lo[mt][3], bh0b, bh1b);
                    }
                }
            }
        }
        cur = (cur + 1 == 3) ? 0 : cur + 1;
    }

#pragma unroll
    for (int mt = 0; mt < 2; mt++) {
#pragma unroll
        for (int nt = 0; nt < 8; nt++) {
#pragma unroll
            for (int half = 0; half < 2; half++) {
                int row = m0 + rA + mt * 16 + qr + half * 8;
                int nb  = row >> 12;
                int t   = row & (TT - 1);
                int col = n0 + cB + nt * 8 + qc * 2;
                int h = col >> 6;
                int d = col & 63;
                float* op = out + (((size_t)(nb * NHH + h)) * TT + t) * DD + d;
                op[0] = acc[mt][nt][half * 2 + 0] + bias[col];
                op[1] = acc[mt][nt][half * 2 + 1] + bias[col + 1];
            }
        }
    }
}

// ---------------- top-k selection: 4 chunks per 256-thread block ------------------
__global__ void select_kernel(const float* __restrict__ mask,
                              const float* __restrict__ bq)
{
    const int sub = threadIdx.x >> 6;
    const int i   = threadIdx.x & 63;
    const int blk = blockIdx.x * 4 + sub;
    const int h   = blockIdx.y;
    const int n   = blockIdx.z;
    __shared__ float norms[4][64];
    __shared__ int flags[4][64];

    const int token = blk * 64 + i;
    const float* kr = g_k + (((size_t)(n * NHH + h)) * TT + token) * DD;
    const float* bqr = bq + h * DD;
    float s = 0.0f;
#pragma unroll
    for (int d = 0; d < DD; d++) { float vv = kr[d] + bqr[d]; s += vv * vv; }
    if (mask[n * TT + token] != 0.0f) s = 0.0f;
    norms[sub][i] = s;
    __syncthreads();

    float mine = norms[sub][i];
    int rank = 0;
    for (int j = 0; j < 64; j++) {
        float nj = norms[sub][j];
        rank += (nj < mine) || (nj == mine && j < i);
    }
    int top = (rank >= 64 - TOPKK) ? 1 : 0;
    flags[sub][i] = top;
    __syncthreads();

    int pos = 0;
    for (int j = 0; j < i; j++) pos += flags[sub][j];
    if (top)
        g_gidx[((size_t)(n * NHH + h)) * (TT / 4) + blk * TOPKK + pos] = token;
    else
        g_lidx[((size_t)(n * NHH + h)) * (3 * TT / 4) + blk * 48 + (i - pos)] = token;
}

// ======== fused local+global flash (tf32), templated chunk body ===================
#define KC     112
#define NCHK   3
#define QSTRW  68
#define VSTRW  72
#define QS_OFF 0
#define KS_OFF (QS_OFF + 128*QSTRW)
#define VS_OFF (KS_OFF + KC*QSTRW)
#define MS_OFF (VS_OFF + KC*VSTRW)
#define LSMEM_WORDS (MS_OFF + KC)

__device__ __forceinline__ float to_tf32(float x)
{
    float r;
    asm("cvt.rna.tf32.f32 %0, %1;" : "=f"(r) : "f"(x));
    return r;
}

__device__ __forceinline__ void mma_tf32(float& d0, float& d1, float& d2, float& d3,
                                         float a0, float a1, float a2, float a3,
                                         float b0, float b1)
{
    asm volatile(
        "mma.sync.aligned.m16n8k8.row.col.f32.tf32.tf32.f32 "
        "{%0,%1,%2,%3}, {%4,%5,%6,%7}, {%8,%9}, {%0,%1,%2,%3};\n"
        : "+f"(d0), "+f"(d1), "+f"(d2), "+f"(d3)
        : "r"(__float_as_uint(a0)), "r"(__float_as_uint(a1)),
          "r"(__float_as_uint(a2)), "r"(__float_as_uint(a3)),
          "r"(__float_as_uint(b0)), "r"(__float_as_uint(b1)));
}

template <int NT>
__device__ __forceinline__ void process_chunk(
    const float* __restrict__ Qs, const float* __restrict__ Ks,
    const float* __restrict__ Vs, const float* __restrict__ Ms,
    int rb, int w16, int qr, int qc, int src0, int src2, bool odd,
    float& m0, float& m1, float& l0, float& l1, float (&o)[8][4])
{
    float s[NT][4];
#pragma unroll
    for (int nt = 0; nt < NT; nt++) {
        s[nt][0] = 0.f; s[nt][1] = 0.f; s[nt][2] = 0.f; s[nt][3] = 0.f;
    }

#pragma unroll
    for (int k8 = 0; k8 < 8; k8++) {
        const int kc0 = k8 * 8 + qc;
        float a0 = Qs[(w16 + qr) * QSTRW + kc0];
        float a1 = Qs[(w16 + qr + 8) * QSTRW + kc0];
        float a2 = Qs[(w16 + qr) * QSTRW + kc0 + 4];
        float a3 = Qs[(w16 + qr + 8) * QSTRW + kc0 + 4];
#pragma unroll
        for (int nt = 0; nt < NT; nt++) {
            float b0 = Ks[(rb + nt * 8 + qr) * QSTRW + kc0];
            float b1 = Ks[(rb + nt * 8 + qr) * QSTRW + kc0 + 4];
            mma_tf32(s[nt][0], s[nt][1], s[nt][2], s[nt][3],
                     a0, a1, a2, a3, b0, b1);
        }
    }

    float cmax0 = -1e30f, cmax1 = -1e30f;
#pragma unroll
    for (int nt = 0; nt < NT; nt++) {
        float mc0 = Ms[rb + nt * 8 + 2 * qc];
        float mc1 = Ms[rb + nt * 8 + 2 * qc + 1];
        s[nt][0] = s[nt][0] * 0.125f + mc0;
        s[nt][1] = s[nt][1] * 0.125f + mc1;
        s[nt][2] = s[nt][2] * 0.125f + mc0;
        s[nt][3] = s[nt][3] * 0.125f + mc1;
        cmax0 = fmaxf(cmax0, fmaxf(s[nt][0], s[nt][1]));
        cmax1 = fmaxf(cmax1, fmaxf(s[nt][2], s[nt][3]));
    }
    cmax0 = fmaxf(cmax0, __shfl_xor_sync(0xffffffffu, cmax0, 1));
    cmax0 = fmaxf(cmax0, __shfl_xor_sync(0xffffffffu, cmax0, 2));
    cmax1 = fmaxf(cmax1, __shfl_xor_sync(0xffffffffu, cmax1, 1));
    cmax1 = fmaxf(cmax1, __shfl_xor_sync(0xffffffffu, cmax1, 2));

    float mn0 = fmaxf(m0, cmax0);
    float mn1 = fmaxf(m1, cmax1);
    float corr0 = __expf(m0 - mn0);
    float corr1 = __expf(m1 - mn1);
    m0 = mn0; m1 = mn1;

    float rs0 = 0.0f, rs1 = 0.0f;
#pragma unroll
    for (int nt = 0; nt < NT; nt++) {
        float p0 = __expf(s[nt][0] - mn0);
        float p1 = __expf(s[nt][1] - mn0);
        float p2 = __expf(s[nt][2] - mn1);
        float p3 = __expf(s[nt][3] - mn1);
        rs0 += p0 + p1; rs1 += p2 + p3;
        s[nt][0] = to_tf32(p0); s[nt][1] = to_tf32(p1);
        s[nt][2] = to_tf32(p2); s[nt][3] = to_tf32(p3);
    }
    rs0 += __shfl_xor_sync(0xffffffffu, rs0, 1);
    rs0 += __shfl_xor_sync(0xffffffffu, rs0, 2);
    rs1 += __shfl_xor_sync(0xffffffffu, rs1, 1);
    rs1 += __shfl_xor_sync(0xffffffffu, rs1, 2);
    l0 = l0 * corr0 + rs0;
    l1 = l1 * corr1 + rs1;

#pragma unroll
    for (int nt = 0; nt < 8; nt++) {
        o[nt][0] *= corr0; o[nt][1] *= corr0;
        o[nt][2] *= corr1; o[nt][3] *= corr1;
    }

#pragma unroll
    for (int kt = 0; kt < NT; kt++) {
        float p0 = s[kt][0], p1 = s[kt][1], p2 = s[kt][2], p3 = s[kt][3];
        float t0 = __shfl_sync(0xffffffffu, p0, src0);
        float t1 = __shfl_sync(0xffffffffu, p1, src0);
        float t2 = __shfl_sync(0xffffffffu, p2, src0);
        float t3 = __shfl_sync(0xffffffffu, p3, src0);
        float u0 = __shfl_sync(0xffffffffu, p0, src2);
        float u1 = __shfl_sync(0xffffffffu, p1, src2);
        float u2 = __shfl_sync(0xffffffffu, p2, src2);
        float u3 = __shfl_sync(0xffffffffu, p3, src2);
        float a0 = odd ? t1 : t0;
        float a1 = odd ? t3 : t2;
        float a2 = odd ? u1 : u0;
        float a3 = odd ? u3 : u2;
#pragma unroll
        for (int nt = 0; nt < 8; nt++) {
            float b0 = Vs[(rb + kt * 8 + qc) * VSTRW + nt * 8 + qr];
            float b1 = Vs[(rb + kt * 8 + qc + 4) * VSTRW + nt * 8 + qr];
            mma_tf32(o[nt][0], o[nt][1], o[nt][2], o[nt][3],
                     a0, a1, a2, a3, b0, b1);
        }
    }
}

__global__ __launch_bounds__(256, 2)
void attn_fused_kernel(const float* __restrict__ mask,
                       float* __restrict__ out)
{
    extern __shared__ float sm[];
    float* Qs = sm + QS_OFF;
    float* Ks = sm + KS_OFF;
    float* Vs = sm + VS_OFF;
    float* Ms = sm + MS_OFF;

    const int qb = blockIdx.x;
    const int h  = blockIdx.y;
    const int n  = blockIdx.z;
    const int tid = threadIdx.x;
    const int lane = tid & 31;
    const int warp = tid >> 5;
    const int qr = lane >> 2;
    const int qc = lane & 3;
    const int w16 = warp * 16;

    const size_t ho = (size_t)(n * NHH + h);
    const float* kb = g_k + ho * TT * DD;
    const float* vb = g_v + ho * TT * DD;
    const int* lix = g_lidx + ho * (3 * TT / 4);
    const int* gix = g_gidx + ho * (TT / 4);

#pragma unroll
    for (int i = 0; i < 8; i++) {
        int idx = tid + i * 256;
        int r = idx >> 4, c4 = idx & 15;
        const float4 qv = *(const float4*)(g_q + (ho * TT + qb * 128 + r) * DD + c4 * 4);
        float* dst = Qs + r * QSTRW + c4 * 4;
        dst[0] = to_tf32(qv.x); dst[1] = to_tf32(qv.y);
        dst[2] = to_tf32(qv.z); dst[3] = to_tf32(qv.w);
    }

    float m0 = -1e30f, m1 = -1e30f, l0 = 0.0f, l1 = 0.0f;
    float o[8][4];
#pragma unroll
    for (int nt = 0; nt < 8; nt++)
#pragma unroll
        for (int e = 0; e < 4; e++) o[nt][e] = 0.0f;

    const int src0 = (qr << 2) + (qc >> 1);
    const int src2 = src0 + 2;
    const bool odd = (qc & 1) != 0;

    for (int ch = 0; ch < NCHK + 1; ch++) {
        const bool glob = (ch == NCHK);
        __syncthreads();
        if (!glob) {
            for (int idx = tid; idx < KC * 16; idx += 256) {
                int r = idx >> 4, c4 = idx & 15;
                int kk = ch * KC + r;
                float4 kv = make_float4(0.f, 0.f, 0.f, 0.f);
                float4 vv = make_float4(0.f, 0.f, 0.f, 0.f);
                float mval = -1e30f;
                if (kk < 288) {
                    int g = qb * 96 - 96 + kk;
                    if (g >= 0 && g < 3 * TT / 4) {
                        int src = lix[g];
                        kv = *(const float4*)(kb + (size_t)src * DD + c4 * 4);
                        vv = *(const float4*)(vb + (size_t)src * DD + c4 * 4);
                        mval = mask[n * TT + src];
                    } else {
                        mval = NEGV;
                    }
                } else if (kk == 288) {
                    kv = *(const float4*)(kb + c4 * 4);
                    vv = *(const float4*)(vb + c4 * 4);
                    mval = 0.0f;
                }
                float* kd = Ks + r * QSTRW + c4 * 4;
                kd[0] = to_tf32(kv.x); kd[1] = to_tf32(kv.y);
                kd[2] = to_tf32(kv.z); kd[3] = to_tf32(kv.w);
                float* vd = Vs + r * VSTRW + c4 * 4;
                vd[0] = to_tf32(vv.x); vd[1] = to_tf32(vv.y);
                vd[2] = to_tf32(vv.z); vd[3] = to_tf32(vv.w);
                if (c4 == 0) Ms[r] = mval;
            }
        } else {
            for (int idx = tid; idx < 96 * 16; idx += 256) {
                int r = idx >> 4, c4 = idx & 15;
                int half = (r >= 48);
                int g = (2 * qb - 1 + half) * 16 + (r - half * 48);
                float4 kv = make_float4(0.f, 0.f, 0.f, 0.f);
                float4 vv = make_float4(0.f, 0.f, 0.f, 0.f);
                float mval = NEGV;
                if (g >= 0 && g < TT / 4) {
                    int src = gix[g];
                    kv = *(const float4*)(kb + (size_t)src * DD + c4 * 4);
                    vv = *(const float4*)(vb + (size_t)src * DD + c4 * 4);
                    mval = mask[n * TT + src];
                }
                float* kd = Ks + r * QSTRW + c4 * 4;
                kd[0] = to_tf32(kv.x); kd[1] = to_tf32(kv.y);
                kd[2] = to_tf32(kv.z); kd[3] = to_tf32(kv.w);
                float* vd = Vs + r * VSTRW + c4 * 4;
                vd[0] = to_tf32(vv.x); vd[1] = to_tf32(vv.y);
                vd[2] = to_tf32(vv.z); vd[3] = to_tf32(vv.w);
                if (c4 == 0) Ms[r] = mval;
            }
        }
        __syncthreads();

        if (!glob) {
            process_chunk<14>(Qs, Ks, Vs, Ms, 0, w16, qr, qc, src0, src2, odd,
                              m0, m1, l0, l1, o);
        } else {
            int rb = (warp >= 4) ? 48 : 0;
            process_chunk<6>(Qs, Ks, Vs, Ms, rb, w16, qr, qc, src0, src2, odd,
                             m0, m1, l0, l1, o);
        }
    }

    float inv0 = 1.0f / l0;
    float inv1 = 1.0f / l1;
    int row0 = qb * 128 + w16 + qr;
    int row1 = row0 + 8;
    float* op0 = out + ((size_t)n * TT + row0) * HIDD + h * DD;
    float* op1 = out + ((size_t)n * TT + row1) * HIDD + h * DD;
#pragma unroll
    for (int nt = 0; nt < 8; nt++) {
        int c0 = nt * 8 + 2 * qc;
#pragma unroll
        for (int e = 0; e < 2; e++) {
            op0[c0 + e] = o[nt][e] * inv0;
            op1[c0 + e] = o[nt][2 + e] * inv1;
        }
    }
}

// ---------------- BOS row (exact q from g_q0) --------------------------------------
__global__ void bos_kernel(const float* __restrict__ mask,
                           float* __restrict__ out)
{
    const int h = blockIdx.x;
    const int n = blockIdx.y;
    const int tid = threadIdx.x;
    __shared__ float sc[TT];
    __shared__ float qs[64];
    __shared__ float red[128];

    const size_t ho = (size_t)(n * NHH + h);
    const float* kb = g_k + ho * TT * DD;
    const float* vb = g_v + ho * TT * DD;
    if (tid < 64) qs[tid] = g_q0[(size_t)n * HIDD + h * DD + tid];
    __syncthreads();

    float lmax = -1e30f;
    for (int t = tid; t < TT; t += 128) {
        const float* kr = kb + (size_t)t * DD;
        float dot = 0.0f;
#pragma unroll
        for (int d = 0; d < 64; d++) dot = fmaf(qs[d], kr[d], dot);
        float s = dot + mask[n * TT + t];
        sc[t] = s;
        lmax = fmaxf(lmax, s);
    }
    red[tid] = lmax;
    __syncthreads();
    for (int off = 64; off > 0; off >>= 1) {
        if (tid < off) red[tid] = fmaxf(red[tid], red[tid + off]);
        __syncthreads();
    }
    float mmax = red[0];
    float lsum = 0.0f;
    for (int t = tid; t < TT; t += 128) {
        float p = __expf(sc[t] - mmax);
        sc[t] = p;
        lsum += p;
    }
    __syncthreads();
    red[tid] = lsum;
    __syncthreads();
    for (int off = 64; off > 0; off >>= 1) {
        if (tid < off) red[tid] += red[tid + off];
        __syncthreads();
    }
    float inv = 1.0f / red[0];
    __syncthreads();
    {
        int half = tid >> 6;
        int d = tid & 63;
        float acc = 0.0f;
        int t0 = half * (TT / 2);
        for (int t = t0; t < t0 + TT / 2; t++)
            acc = fmaf(sc[t], vb[(size_t)t * DD + d], acc);
        red[tid] = acc;
    }
    __syncthreads();
    if (tid < 64)
        out[((size_t)n * TT) * HIDD + h * DD + tid] =
            (red[tid] + red[tid + 64]) * inv;
}

// ---------------- launch ----------------------------------------------------------
extern "C" void kernel_launch(void* const* d_in, const int* in_sizes, int n_in,
                              void* d_out, int out_size)
{
    (void)in_sizes; (void)n_in; (void)out_size;
    const float* hs   = (const float*)d_in[0];
    const float* mask = (const float*)d_in[1];
    const float* Wq   = (const float*)d_in[2];
    const float* bq   = (const float*)d_in[3];
    const float* Wk   = (const float*)d_in[4];
    const float* bk   = (const float*)d_in[5];
    const float* Wv   = (const float*)d_in[6];
    const float* bv   = (const float*)d_in[7];
    float* out = (float*)d_out;

    float *qp, *kp, *vp;
    cudaGetSymbolAddress((void**)&qp, g_q);
    cudaGetSymbolAddress((void**)&kp, g_k);
    cudaGetSymbolAddress((void**)&vp, g_v);
    uint2 *ahp, *alp, *afh, *afl, *whp, *wlp, *wfh;
    cudaGetSymbolAddress((void**)&ahp, g_Ahi4);
    cudaGetSymbolAddress((void**)&alp, g_Alo4);
    cudaGetSymbolAddress((void**)&afh, g_Afh4);
    cudaGetSymbolAddress((void**)&afl, g_Afl4);
    cudaGetSymbolAddress((void**)&whp, g_Whi4);
    cudaGetSymbolAddress((void**)&wlp, g_Wlo4);
    cudaGetSymbolAddress((void**)&wfh, g_Wfh4);

    {
        int n4a = NB * TT * HIDD / 4;
        cvt_a_kernel<<<(n4a + 255) / 256, 256>>>(hs, ahp, alp, afh, afl, n4a);
        int n4w = HIDD * HIDD / 4;
        cvt_w_kernel<<<dim3((n4w + 255) / 256, 3), 256>>>(Wq, Wk, Wv, whp, wlp, wfh, n4w);
        q0_kernel<<<dim3(HIDD, NB), 128>>>(hs, Wq, bq);
    }

    {
        cudaFuncSetAttribute(gemm_all_kernel,
                             cudaFuncAttributeMaxDynamicSharedMemorySize, GSMEMB);
        gemm_all_kernel<<<dim3(HIDD / 128, (NB * TT) / 128, 3), 256, GSMEMB>>>(
            bq, bk, bv, qp, kp, vp);
    }

    select_kernel<<<dim3(TT / 256, NHH, NB), 256>>>(mask, bq);

    size_t lsmem = (size_t)LSMEM_WORDS * sizeof(float);
    cudaFuncSetAttribute(attn_fused_kernel,
                         cudaFuncAttributeMaxDynamicSharedMemorySize, (int)lsmem);
    attn_fused_kernel<<<dim3(TT / 128, NHH, NB), 256, lsmem>>>(mask, out);

    bos_kernel<<<dim3(NHH, NB), 128>>>(mask, out);
}